// round 13
// baseline (speedup 1.0000x reference)
#include <cuda_runtime.h>
#include <cuda_fp16.h>
#include <cstdint>

// Problem constants
#define HEADS   6
#define HD      32      // head_dim
#define DIMM    192
#define NWIN    256     // tokens per 16x16 window
#define KS_STRIDE 40    // half elements per K/V row in smem (80B rows, conflict-free)
#define LOG2E   1.4426950408889634f
#define QK_SCALE 0.17677669529663687f   // 32^-0.5

__device__ __forceinline__ float rcpf(float x) {
    float y; asm("rcp.approx.f32 %0, %1;" : "=f"(y) : "f"(x)); return y;
}
__device__ __forceinline__ uint32_t ex2h2(uint32_t a) {
    uint32_t d; asm("ex2.approx.f16x2 %0, %1;" : "=r"(d) : "r"(a)); return d;
}
__device__ __forceinline__ uint32_t hadd2u(uint32_t a, uint32_t b) {
    uint32_t d; asm("add.f16x2 %0, %1, %2;" : "=r"(d) : "r"(a), "r"(b)); return d;
}
__device__ __forceinline__ float2 h22f2(uint32_t h) {
    float2 f;
    asm("{\n\t.reg .f16 lo, hi;\n\tmov.b32 {lo, hi}, %2;\n\t"
        "cvt.f32.f16 %0, lo;\n\tcvt.f32.f16 %1, hi;\n\t}"
        : "=f"(f.x), "=f"(f.y) : "r"(h));
    return f;
}
// pack two floats into f16x2 register: lo = first arg
__device__ __forceinline__ uint32_t pack_h2(float lo, float hi) {
    uint32_t r;
    asm("cvt.rn.f16x2.f32 %0, %1, %2;" : "=r"(r) : "f"(hi), "f"(lo));
    return r;
}
__device__ __forceinline__ uint32_t smem_u32(const void* p) {
    uint32_t a;
    asm("{ .reg .u64 t; cvta.to.shared.u64 t, %1; cvt.u32.u64 %0, t; }"
        : "=r"(a) : "l"(p));
    return a;
}
__device__ __forceinline__ void ldsm4(uint32_t* r, uint32_t addr) {
    asm volatile("ldmatrix.sync.aligned.m8n8.x4.shared.b16 {%0,%1,%2,%3}, [%4];"
        : "=r"(r[0]), "=r"(r[1]), "=r"(r[2]), "=r"(r[3]) : "r"(addr));
}
__device__ __forceinline__ void ldsm4t(uint32_t* r, uint32_t addr) {
    asm volatile("ldmatrix.sync.aligned.m8n8.x4.trans.shared.b16 {%0,%1,%2,%3}, [%4];"
        : "=r"(r[0]), "=r"(r[1]), "=r"(r[2]), "=r"(r[3]) : "r"(addr));
}

// f16-accumulate MMA: {c0,c1} += A * B   (C/D are f16x2 pairs)
#define MMAH(c0, c1, a, b0, b1)                                               \
    asm("mma.sync.aligned.m16n8k16.row.col.f16.f16.f16.f16 "                  \
        "{%0,%1}, {%2,%3,%4,%5}, {%6,%7}, {%0,%1};"                           \
        : "+r"(c0), "+r"(c1)                                                  \
        : "r"((a)[0]), "r"((a)[1]), "r"((a)[2]), "r"((a)[3]),                 \
          "r"(b0), "r"(b1))

// f32-accumulate MMA: C += A * B
#define MMAF(c, a, b0, b1)                                                    \
    asm("mma.sync.aligned.m16n8k16.row.col.f32.f16.f16.f32 "                  \
        "{%0,%1,%2,%3}, {%4,%5,%6,%7}, {%8,%9}, {%0,%1,%2,%3};"               \
        : "+f"((c)[0]), "+f"((c)[1]), "+f"((c)[2]), "+f"((c)[3])              \
        : "r"((a)[0]), "r"((a)[1]), "r"((a)[2]), "r"((a)[3]),                 \
          "r"(b0), "r"(b1))

__global__ __launch_bounds__(256, 2)
void winattn_kernel(const float* __restrict__ qkv,
                    const float* __restrict__ bias_table,
                    float* __restrict__ out)
{
    // Ks padded +16 rows so the final K-prefetch overread stays inside Ks.
    __shared__ half     Ks[(NWIN + 16) * KS_STRIDE];  // 21760 B
    __shared__ half     Vs[NWIN * KS_STRIDE];         // 20480 B
    __shared__ uint32_t bh[961];                      //  3844 B: half2 (b[i+1], b[i]) * log2e

    const int tid  = threadIdx.x;
    const int bid  = blockIdx.x;
    const int head = bid % HEADS;
    const int win  = (bid / HEADS) & 255;
    const int b    = bid / (HEADS * 256);

    const int wh0 = (win >> 4) << 4;   // window top row in the image
    const int ww0 = (win & 15) << 4;   // window left col

    const long long plane = 65536LL * DIMM;

    // ---------------- load K, V into smem (fp16, identical layout) --------
    {
        const float* kbase = qkv + (2 + b) * plane + head * HD;
        const float* vbase = qkv + (4 + b) * plane + head * HD;
        for (int vi = tid; vi < NWIN * (HD / 4); vi += 256) {
            const int p  = vi >> 3;            // window pixel 0..255
            const int c4 = (vi & 7) * 4;       // channel 0,4,...,28
            const int grow = (wh0 + (p >> 4)) * 256 + ww0 + (p & 15);
            const float4 kv = *(const float4*)(kbase + (long long)grow * DIMM + c4);
            const float4 vv = *(const float4*)(vbase + (long long)grow * DIMM + c4);
            *(half2*)&Ks[p * KS_STRIDE + c4]     = __floats2half2_rn(kv.x, kv.y);
            *(half2*)&Ks[p * KS_STRIDE + c4 + 2] = __floats2half2_rn(kv.z, kv.w);
            *(half2*)&Vs[p * KS_STRIDE + c4]     = __floats2half2_rn(vv.x, vv.y);
            *(half2*)&Vs[p * KS_STRIDE + c4 + 2] = __floats2half2_rn(vv.z, vv.w);
        }
        // bias pair table as half2: low half = b[i+1], high half = b[i]
        for (int i = tid; i < 961; i += 256) {
            const float lo = bias_table[i * HEADS + head] * LOG2E;
            const float hi = (i < 960 ? bias_table[(i + 1) * HEADS + head] : 0.f) * LOG2E;
            bh[i] = pack_h2(hi, lo);
        }
    }

    // ---------------- per-warp Q fragments (32 rows per warp) -------------
    const int warp  = tid >> 5;
    const int lane  = tid & 31;
    const int g     = lane >> 2;     // groupID 0..7
    const int t     = lane & 3;      // thread-in-group
    const int wbase = warp * 32;     // this warp's 32 query rows

    uint32_t af[2][2][4];            // [mtile][kstep][4 regs], Q * scale * log2e
    int ar0;                         // bias row code for mt0 row rA (mt1 = +31)
    {
        const float* qbase = qkv + b * plane + head * HD;
        const float qs = QK_SCALE * LOG2E;
        const int rA = wbase + g;
        ar0 = ((rA >> 4) + 15) * 31 + (rA & 15) + 15;
        #pragma unroll
        for (int mt = 0; mt < 2; mt++) {
            const int r0 = wbase + mt * 16 + g;
            const int r1 = r0 + 8;
            const int g0 = (wh0 + (r0 >> 4)) * 256 + ww0 + (r0 & 15);
            const int g1 = (wh0 + (r1 >> 4)) * 256 + ww0 + (r1 & 15);
            const float* qA = qbase + (long long)g0 * DIMM;
            const float* qB = qbase + (long long)g1 * DIMM;
            #pragma unroll
            for (int ks = 0; ks < 2; ks++) {
                const int c0 = ks * 16 + 2 * t;
                float2 f;
                f = *(const float2*)(qA + c0);
                af[mt][ks][0] = pack_h2(f.x * qs, f.y * qs);
                f = *(const float2*)(qB + c0);
                af[mt][ks][1] = pack_h2(f.x * qs, f.y * qs);
                f = *(const float2*)(qA + c0 + 8);
                af[mt][ks][2] = pack_h2(f.x * qs, f.y * qs);
                f = *(const float2*)(qB + c0 + 8);
                af[mt][ks][3] = pack_h2(f.x * qs, f.y * qs);
            }
        }
    }

    __syncthreads();

    // ---------------- fragment addresses (incremented per iter) -----------
    const int lm = lane >> 3;
    const int lr = lane & 7;
    uint32_t kaddr = smem_u32(&Ks[((lm >> 1) * 8 + lr) * KS_STRIDE + (lm & 1) * 8]);
    uint32_t vaddr = smem_u32(&Vs[(lane & 7) * KS_STRIDE + (lane >> 3) * 8]);
    const uint32_t VROW8 = 8 * KS_STRIDE * 2;    // +8 j rows
    const uint32_t JSTEP = 16 * KS_STRIDE * 2;   // +16 rows per iter

    // Bias pair-table index for mt0 (mt1 = +31); decrements by 31 per block.
    int i00 = ar0 - (2 * t + 1);

    float o[2][4][4] = {};    // [mtile][d-tile][4] fp32 accumulators
    float rs[2][2]   = {};    // [mtile][row-half] fp32 row-sum accumulators

    // ---------------- main loop: 16-col blocks, K double-buffered ---------
    uint32_t bf[2][2][4];     // [parity][kstep][4]
    ldsm4(bf[0][0], kaddr);
    ldsm4(bf[0][1], kaddr + 32);
    kaddr += JSTEP;

    #pragma unroll 2
    for (int it = 0; it < 16; it++) {
        const int pc = it & 1, pn = pc ^ 1;

        // V fragments for this block (consumed ~35 instrs later)
        uint32_t bvA[4], bvB[4];
        ldsm4t(bvA, vaddr);
        ldsm4t(bvB, vaddr + VROW8);
        vaddr += JSTEP;

        // Prefetch next block's K (iter 15 overreads into Ks padding)
        ldsm4(bf[pn][0], kaddr);
        ldsm4(bf[pn][1], kaddr + 32);
        kaddr += JSTEP;

        #pragma unroll
        for (int mt = 0; mt < 2; mt++) {
            const int ib = i00 + mt * 31;
            uint32_t sc0 = bh[ib];       // (rA, cols c,c+1)
            uint32_t sc1 = bh[ib + 8];   // (rB, cols c,c+1)
            uint32_t sc2 = bh[ib - 8];   // (rA, cols c+8,c+9)
            uint32_t sc3 = sc0;          // (rB, cols c+8,c+9) == bh[ib]

            // S = Q K^T + bias   (fp16 accum, log2 units)
            MMAH(sc0, sc1, af[mt][0], bf[pc][0][0], bf[pc][0][1]);
            MMAH(sc0, sc1, af[mt][1], bf[pc][1][0], bf[pc][1][1]);
            MMAH(sc2, sc3, af[mt][0], bf[pc][0][2], bf[pc][0][3]);
            MMAH(sc2, sc3, af[mt][1], bf[pc][1][2], bf[pc][1][3]);

            // P = 2^S (f16x2) — C-frags ARE the PV A-frags
            uint32_t pa[4];
            pa[0] = ex2h2(sc0);
            pa[1] = ex2h2(sc1);
            pa[2] = ex2h2(sc2);
            pa[3] = ex2h2(sc3);

            // row sums: pairwise fp16, accumulate fp32
            const float2 fA = h22f2(hadd2u(pa[0], pa[2]));
            rs[mt][0] += fA.x + fA.y;
            const float2 fB = h22f2(hadd2u(pa[1], pa[3]));
            rs[mt][1] += fB.x + fB.y;

            // O += P * V
            MMAF(o[mt][0], pa, bvA[0], bvB[0]);
            MMAF(o[mt][1], pa, bvA[1], bvB[1]);
            MMAF(o[mt][2], pa, bvA[2], bvB[2]);
            MMAF(o[mt][3], pa, bvA[3], bvB[3]);
        }

        i00 -= 31;
    }

    // ---------------- normalize and write output --------------------------
    #pragma unroll
    for (int mt = 0; mt < 2; mt++) {
        float r0 = rs[mt][0], r1 = rs[mt][1];
        r0 += __shfl_xor_sync(0xFFFFFFFFu, r0, 1);
        r0 += __shfl_xor_sync(0xFFFFFFFFu, r0, 2);
        r1 += __shfl_xor_sync(0xFFFFFFFFu, r1, 1);
        r1 += __shfl_xor_sync(0xFFFFFFFFu, r1, 2);
        const float inv0 = rcpf(r0);
        const float inv1 = rcpf(r1);

        const int rA = wbase + mt * 16 + g;
        const int rB = rA + 8;
        const long long gA = b * 65536LL + (wh0 + (rA >> 4)) * 256 + ww0 + (rA & 15);
        const long long gB = b * 65536LL + (wh0 + (rB >> 4)) * 256 + ww0 + (rB & 15);
        float* oA = out + gA * DIMM + head * HD;
        float* oB = out + gB * DIMM + head * HD;
        #pragma unroll
        for (int dt = 0; dt < 4; dt++) {
            const int d = dt * 8 + 2 * t;
            *(float2*)(oA + d) = make_float2(o[mt][dt][0] * inv0, o[mt][dt][1] * inv0);
            *(float2*)(oB + d) = make_float2(o[mt][dt][2] * inv1, o[mt][dt][3] * inv1);
        }
    }
}

extern "C" void kernel_launch(void* const* d_in, const int* in_sizes, int n_in,
                              void* d_out, int out_size)
{
    (void)in_sizes; (void)n_in; (void)out_size;
    const float* qkv        = (const float*)d_in[0];
    const float* bias_table = (const float*)d_in[1];
    float* out              = (float*)d_out;

    // 2 batches * 256 windows * 6 heads = 3072 CTAs, 256 threads each
    winattn_kernel<<<3072, 256>>>(qkv, bias_table, out);
}

// round 14
// speedup vs baseline: 1.1783x; 1.1783x over previous
#include <cuda_runtime.h>
#include <cuda_fp16.h>
#include <cstdint>

// Problem constants
#define HEADS   6
#define HD      32      // head_dim
#define DIMM    192
#define NWIN    256     // tokens per 16x16 window
#define KS_STRIDE 40    // half elements per K/V row in smem (80B rows, conflict-free)
#define LOG2E   1.4426950408889634f
#define QK_SCALE 0.17677669529663687f   // 32^-0.5

__device__ __forceinline__ float rcpf(float x) {
    float y; asm("rcp.approx.f32 %0, %1;" : "=f"(y) : "f"(x)); return y;
}
__device__ __forceinline__ uint32_t ex2h2(uint32_t a) {
    uint32_t d; asm("ex2.approx.f16x2 %0, %1;" : "=r"(d) : "r"(a)); return d;
}
__device__ __forceinline__ uint32_t hadd2u(uint32_t a, uint32_t b) {
    uint32_t d; asm("add.f16x2 %0, %1, %2;" : "=r"(d) : "r"(a), "r"(b)); return d;
}
__device__ __forceinline__ float2 h22f2(uint32_t h) {
    float2 f;
    asm("{\n\t.reg .f16 lo, hi;\n\tmov.b32 {lo, hi}, %2;\n\t"
        "cvt.f32.f16 %0, lo;\n\tcvt.f32.f16 %1, hi;\n\t}"
        : "=f"(f.x), "=f"(f.y) : "r"(h));
    return f;
}
// pack two floats into f16x2 register: lo = first arg
__device__ __forceinline__ uint32_t pack_h2(float lo, float hi) {
    uint32_t r;
    asm("cvt.rn.f16x2.f32 %0, %1, %2;" : "=r"(r) : "f"(hi), "f"(lo));
    return r;
}
__device__ __forceinline__ uint32_t smem_u32(const void* p) {
    uint32_t a;
    asm("{ .reg .u64 t; cvta.to.shared.u64 t, %1; cvt.u32.u64 %0, t; }"
        : "=r"(a) : "l"(p));
    return a;
}
__device__ __forceinline__ void ldsm4(uint32_t* r, uint32_t addr) {
    asm volatile("ldmatrix.sync.aligned.m8n8.x4.shared.b16 {%0,%1,%2,%3}, [%4];"
        : "=r"(r[0]), "=r"(r[1]), "=r"(r[2]), "=r"(r[3]) : "r"(addr));
}
__device__ __forceinline__ void ldsm4t(uint32_t* r, uint32_t addr) {
    asm volatile("ldmatrix.sync.aligned.m8n8.x4.trans.shared.b16 {%0,%1,%2,%3}, [%4];"
        : "=r"(r[0]), "=r"(r[1]), "=r"(r[2]), "=r"(r[3]) : "r"(addr));
}

// f16-accumulate MMA: {c0,c1} += A * B   (C/D are f16x2 pairs)
#define MMAH(c0, c1, a, b0, b1)                                               \
    asm("mma.sync.aligned.m16n8k16.row.col.f16.f16.f16.f16 "                  \
        "{%0,%1}, {%2,%3,%4,%5}, {%6,%7}, {%0,%1};"                           \
        : "+r"(c0), "+r"(c1)                                                  \
        : "r"((a)[0]), "r"((a)[1]), "r"((a)[2]), "r"((a)[3]),                 \
          "r"(b0), "r"(b1))

// f32-accumulate MMA: C += A * B
#define MMAF(c, a, b0, b1)                                                    \
    asm("mma.sync.aligned.m16n8k16.row.col.f32.f16.f16.f32 "                  \
        "{%0,%1,%2,%3}, {%4,%5,%6,%7}, {%8,%9}, {%0,%1,%2,%3};"               \
        : "+f"((c)[0]), "+f"((c)[1]), "+f"((c)[2]), "+f"((c)[3])              \
        : "r"((a)[0]), "r"((a)[1]), "r"((a)[2]), "r"((a)[3]),                 \
          "r"(b0), "r"(b1))

__global__ __launch_bounds__(512, 2)
void winattn_kernel(const float* __restrict__ qkv,
                    const float* __restrict__ bias_table,
                    float* __restrict__ out)
{
    // Ks padded +16 rows so the final K-prefetch overread stays inside Ks.
    __shared__ half     Ks[(NWIN + 16) * KS_STRIDE];  // 21760 B
    __shared__ half     Vs[NWIN * KS_STRIDE];         // 20480 B
    __shared__ uint32_t bh[961];                      //  3844 B: half2 (b[i+1], b[i]) * log2e

    const int tid  = threadIdx.x;
    const int bid  = blockIdx.x;
    const int head = bid % HEADS;
    const int win  = (bid / HEADS) & 255;
    const int b    = bid / (HEADS * 256);

    const int wh0 = (win >> 4) << 4;   // window top row in the image
    const int ww0 = (win & 15) << 4;   // window left col

    const long long plane = 65536LL * DIMM;

    // ---------------- load K, V into smem (fp16, identical layout) --------
    {
        const float* kbase = qkv + (2 + b) * plane + head * HD;
        const float* vbase = qkv + (4 + b) * plane + head * HD;
        for (int vi = tid; vi < NWIN * (HD / 4); vi += 512) {
            const int p  = vi >> 3;            // window pixel 0..255
            const int c4 = (vi & 7) * 4;       // channel 0,4,...,28
            const int grow = (wh0 + (p >> 4)) * 256 + ww0 + (p & 15);
            const float4 kv = *(const float4*)(kbase + (long long)grow * DIMM + c4);
            const float4 vv = *(const float4*)(vbase + (long long)grow * DIMM + c4);
            *(half2*)&Ks[p * KS_STRIDE + c4]     = __floats2half2_rn(kv.x, kv.y);
            *(half2*)&Ks[p * KS_STRIDE + c4 + 2] = __floats2half2_rn(kv.z, kv.w);
            *(half2*)&Vs[p * KS_STRIDE + c4]     = __floats2half2_rn(vv.x, vv.y);
            *(half2*)&Vs[p * KS_STRIDE + c4 + 2] = __floats2half2_rn(vv.z, vv.w);
        }
        // bias pair table as half2: low half = b[i+1], high half = b[i]
        for (int i = tid; i < 961; i += 512) {
            const float lo = bias_table[i * HEADS + head] * LOG2E;
            const float hi = (i < 960 ? bias_table[(i + 1) * HEADS + head] : 0.f) * LOG2E;
            bh[i] = pack_h2(hi, lo);   // low half = hi-index value
        }
    }

    // ---------------- per-warp Q fragments (16 rows per warp) -------------
    const int warp  = tid >> 5;
    const int lane  = tid & 31;
    const int g     = lane >> 2;     // groupID 0..7
    const int t     = lane & 3;      // thread-in-group
    const int wbase = warp * 16;     // this warp's 16 query rows

    uint32_t af[2][4];               // [kstep][4 regs], Q * scale * log2e
    int ar0;                         // bias row code for row rA (rB = +8)
    {
        const float* qbase = qkv + b * plane + head * HD;
        const float qs = QK_SCALE * LOG2E;
        const int rA = wbase + g;
        const int rB = rA + 8;
        ar0 = ((rA >> 4) + 15) * 31 + (rA & 15) + 15;
        const int gA = (wh0 + (rA >> 4)) * 256 + ww0 + (rA & 15);
        const int gB = (wh0 + (rB >> 4)) * 256 + ww0 + (rB & 15);
        const float* qA = qbase + (long long)gA * DIMM;
        const float* qB = qbase + (long long)gB * DIMM;
        #pragma unroll
        for (int ks = 0; ks < 2; ks++) {
            const int c0 = ks * 16 + 2 * t;
            float2 f;
            f = *(const float2*)(qA + c0);
            af[ks][0] = pack_h2(f.x * qs, f.y * qs);
            f = *(const float2*)(qB + c0);
            af[ks][1] = pack_h2(f.x * qs, f.y * qs);
            f = *(const float2*)(qA + c0 + 8);
            af[ks][2] = pack_h2(f.x * qs, f.y * qs);
            f = *(const float2*)(qB + c0 + 8);
            af[ks][3] = pack_h2(f.x * qs, f.y * qs);
        }
    }

    __syncthreads();

    // ---------------- fragment addresses (incremented per iter) -----------
    const int lm = lane >> 3;
    const int lr = lane & 7;
    uint32_t kaddr = smem_u32(&Ks[((lm >> 1) * 8 + lr) * KS_STRIDE + (lm & 1) * 8]);
    uint32_t vaddr = smem_u32(&Vs[(lane & 7) * KS_STRIDE + (lane >> 3) * 8]);
    const uint32_t VROW8 = 8 * KS_STRIDE * 2;    // +8 j rows
    const uint32_t JSTEP = 16 * KS_STRIDE * 2;   // +16 rows per iter

    // Bias pair-table index; decrements by 31 each 16-col block.
    int i00 = ar0 - (2 * t + 1);

    float o[4][4] = {};       // [d-tile][4] fp32 accumulators
    float rs0 = 0.f, rs1 = 0.f;

    // ---------------- main loop: K fragments double-buffered --------------
    uint32_t bf[2][2][4];     // [parity][kstep][4]
    ldsm4(bf[0][0], kaddr);
    ldsm4(bf[0][1], kaddr + 32);
    kaddr += JSTEP;

    #pragma unroll 2
    for (int it = 0; it < 16; it++) {
        const int pc = it & 1, pn = pc ^ 1;

        // V fragments for this block (consumed after MMAH/ex2 chain)
        uint32_t bvA[4], bvB[4];
        ldsm4t(bvA, vaddr);
        ldsm4t(bvB, vaddr + VROW8);
        vaddr += JSTEP;

        // Prefetch next block's K (iter 15 overreads into Ks padding)
        ldsm4(bf[pn][0], kaddr);
        ldsm4(bf[pn][1], kaddr + 32);
        kaddr += JSTEP;

        // bias half2 pairs -> initialize f16 S accumulators
        uint32_t sc0 = bh[i00];          // (rA, cols c,c+1)
        uint32_t sc1 = bh[i00 + 8];      // (rB, cols c,c+1)
        uint32_t sc2 = bh[i00 - 8];      // (rA, cols c+8,c+9)
        uint32_t sc3 = sc0;              // (rB, cols c+8,c+9) == bh[i00]

        // S = Q K^T + bias   (fp16 accum, log2 units) — K frags already resident
        MMAH(sc0, sc1, af[0], bf[pc][0][0], bf[pc][0][1]);
        MMAH(sc0, sc1, af[1], bf[pc][1][0], bf[pc][1][1]);
        MMAH(sc2, sc3, af[0], bf[pc][0][2], bf[pc][0][3]);
        MMAH(sc2, sc3, af[1], bf[pc][1][2], bf[pc][1][3]);

        // P = 2^S  (f16x2) — C-frags ARE the PV A-frags
        uint32_t pa[4];
        pa[0] = ex2h2(sc0);
        pa[1] = ex2h2(sc1);
        pa[2] = ex2h2(sc2);
        pa[3] = ex2h2(sc3);

        // row sums: pairwise in fp16, accumulate fp32
        const float2 fA = h22f2(hadd2u(pa[0], pa[2]));
        rs0 += fA.x + fA.y;
        const float2 fB = h22f2(hadd2u(pa[1], pa[3]));
        rs1 += fB.x + fB.y;

        // O += P * V
        MMAF(o[0], pa, bvA[0], bvB[0]);
        MMAF(o[1], pa, bvA[1], bvB[1]);
        MMAF(o[2], pa, bvA[2], bvB[2]);
        MMAF(o[3], pa, bvA[3], bvB[3]);

        i00 -= 31;
    }

    // ---------------- normalize and write output --------------------------
    rs0 += __shfl_xor_sync(0xFFFFFFFFu, rs0, 1);
    rs0 += __shfl_xor_sync(0xFFFFFFFFu, rs0, 2);
    rs1 += __shfl_xor_sync(0xFFFFFFFFu, rs1, 1);
    rs1 += __shfl_xor_sync(0xFFFFFFFFu, rs1, 2);
    const float inv0 = rcpf(rs0);
    const float inv1 = rcpf(rs1);

    const int rA = wbase + g;
    const int rB = rA + 8;
    const long long gA = b * 65536LL + (wh0 + (rA >> 4)) * 256 + ww0 + (rA & 15);
    const long long gB = b * 65536LL + (wh0 + (rB >> 4)) * 256 + ww0 + (rB & 15);
    float* oA = out + gA * DIMM + head * HD;
    float* oB = out + gB * DIMM + head * HD;
    #pragma unroll
    for (int dt = 0; dt < 4; dt++) {
        const int d = dt * 8 + 2 * t;
        *(float2*)(oA + d) = make_float2(o[dt][0] * inv0, o[dt][1] * inv0);
        *(float2*)(oB + d) = make_float2(o[dt][2] * inv1, o[dt][3] * inv1);
    }
}

extern "C" void kernel_launch(void* const* d_in, const int* in_sizes, int n_in,
                              void* d_out, int out_size)
{
    (void)in_sizes; (void)n_in; (void)out_size;
    const float* qkv        = (const float*)d_in[0];
    const float* bias_table = (const float*)d_in[1];
    float* out              = (float*)d_out;

    // 2 batches * 256 windows * 6 heads = 3072 CTAs, 512 threads each
    winattn_kernel<<<3072, 512>>>(qkv, bias_table, out);
}

// round 15
// speedup vs baseline: 1.1911x; 1.0108x over previous
#include <cuda_runtime.h>
#include <cuda_fp16.h>
#include <cstdint>

// Problem constants
#define HEADS   6
#define HD      32      // head_dim
#define DIMM    192
#define NWIN    256     // tokens per 16x16 window
#define KS_STRIDE 40    // half elements per K/V row in smem (80B rows, conflict-free)
#define LOG2E   1.4426950408889634f
#define QK_SCALE 0.17677669529663687f   // 32^-0.5

__device__ __forceinline__ float rcpf(float x) {
    float y; asm("rcp.approx.f32 %0, %1;" : "=f"(y) : "f"(x)); return y;
}
__device__ __forceinline__ uint32_t ex2h2(uint32_t a) {
    uint32_t d; asm("ex2.approx.f16x2 %0, %1;" : "=r"(d) : "r"(a)); return d;
}
__device__ __forceinline__ uint32_t hadd2u(uint32_t a, uint32_t b) {
    uint32_t d; asm("add.f16x2 %0, %1, %2;" : "=r"(d) : "r"(a), "r"(b)); return d;
}
__device__ __forceinline__ float2 h22f2(uint32_t h) {
    float2 f;
    asm("{\n\t.reg .f16 lo, hi;\n\tmov.b32 {lo, hi}, %2;\n\t"
        "cvt.f32.f16 %0, lo;\n\tcvt.f32.f16 %1, hi;\n\t}"
        : "=f"(f.x), "=f"(f.y) : "r"(h));
    return f;
}
// pack two floats into f16x2 register: lo = first arg
__device__ __forceinline__ uint32_t pack_h2(float lo, float hi) {
    uint32_t r;
    asm("cvt.rn.f16x2.f32 %0, %1, %2;" : "=r"(r) : "f"(hi), "f"(lo));
    return r;
}
__device__ __forceinline__ uint32_t smem_u32(const void* p) {
    uint32_t a;
    asm("{ .reg .u64 t; cvta.to.shared.u64 t, %1; cvt.u32.u64 %0, t; }"
        : "=r"(a) : "l"(p));
    return a;
}
__device__ __forceinline__ void ldsm4(uint32_t* r, uint32_t addr) {
    asm volatile("ldmatrix.sync.aligned.m8n8.x4.shared.b16 {%0,%1,%2,%3}, [%4];"
        : "=r"(r[0]), "=r"(r[1]), "=r"(r[2]), "=r"(r[3]) : "r"(addr));
}
__device__ __forceinline__ void ldsm4t(uint32_t* r, uint32_t addr) {
    asm volatile("ldmatrix.sync.aligned.m8n8.x4.trans.shared.b16 {%0,%1,%2,%3}, [%4];"
        : "=r"(r[0]), "=r"(r[1]), "=r"(r[2]), "=r"(r[3]) : "r"(addr));
}

// f16-accumulate MMA: {c0,c1} += A * B   (C/D are f16x2 pairs)
#define MMAH(c0, c1, a, b0, b1)                                               \
    asm("mma.sync.aligned.m16n8k16.row.col.f16.f16.f16.f16 "                  \
        "{%0,%1}, {%2,%3,%4,%5}, {%6,%7}, {%0,%1};"                           \
        : "+r"(c0), "+r"(c1)                                                  \
        : "r"((a)[0]), "r"((a)[1]), "r"((a)[2]), "r"((a)[3]),                 \
          "r"(b0), "r"(b1))

// f32-accumulate MMA: C += A * B
#define MMAF(c, a, b0, b1)                                                    \
    asm("mma.sync.aligned.m16n8k16.row.col.f32.f16.f16.f32 "                  \
        "{%0,%1,%2,%3}, {%4,%5,%6,%7}, {%8,%9}, {%0,%1,%2,%3};"               \
        : "+f"((c)[0]), "+f"((c)[1]), "+f"((c)[2]), "+f"((c)[3])              \
        : "r"((a)[0]), "r"((a)[1]), "r"((a)[2]), "r"((a)[3]),                 \
          "r"(b0), "r"(b1))

__global__ __launch_bounds__(512, 2)
void winattn_kernel(const float* __restrict__ qkv,
                    const float* __restrict__ bias_table,
                    float* __restrict__ out)
{
    __shared__ half     Ks[NWIN * KS_STRIDE];   // 20480 B: K, row-major (j, k)
    __shared__ half     Vs[NWIN * KS_STRIDE];   // 20480 B: V, row-major (j, d)
    __shared__ uint32_t bh[961];                //  3844 B: half2 (b[i+1], b[i]) * log2e

    const int tid  = threadIdx.x;
    const int bid  = blockIdx.x;
    const int head = bid % HEADS;
    const int win  = (bid / HEADS) & 255;
    const int b    = bid / (HEADS * 256);

    const int wh0 = (win >> 4) << 4;   // window top row in the image
    const int ww0 = (win & 15) << 4;   // window left col

    const long long plane = 65536LL * DIMM;

    // ---------------- load K, V into smem (fp16), STS.64-packed -----------
    {
        const float* kbase = qkv + (2 + b) * plane + head * HD;
        const float* vbase = qkv + (4 + b) * plane + head * HD;
        for (int vi = tid; vi < NWIN * (HD / 4); vi += 512) {
            const int p  = vi >> 3;            // window pixel 0..255
            const int c4 = (vi & 7) * 4;       // channel 0,4,...,28
            const int grow = (wh0 + (p >> 4)) * 256 + ww0 + (p & 15);
            const float4 kv = *(const float4*)(kbase + (long long)grow * DIMM + c4);
            const float4 vv = *(const float4*)(vbase + (long long)grow * DIMM + c4);
            uint2 kk, vvv;
            kk.x  = pack_h2(kv.x, kv.y);  kk.y  = pack_h2(kv.z, kv.w);
            vvv.x = pack_h2(vv.x, vv.y);  vvv.y = pack_h2(vv.z, vv.w);
            *(uint2*)&Ks[p * KS_STRIDE + c4] = kk;
            *(uint2*)&Vs[p * KS_STRIDE + c4] = vvv;
        }
        // bias pair table as half2: low half = b[i+1], high half = b[i]
        for (int i = tid; i < 961; i += 512) {
            const float lo = bias_table[i * HEADS + head] * LOG2E;
            const float hi = (i < 960 ? bias_table[(i + 1) * HEADS + head] : 0.f) * LOG2E;
            bh[i] = pack_h2(hi, lo);   // low half = hi-index value
        }
    }

    // ---------------- per-warp Q fragments (16 rows per warp) -------------
    const int warp  = tid >> 5;
    const int lane  = tid & 31;
    const int g     = lane >> 2;     // groupID 0..7
    const int t     = lane & 3;      // thread-in-group
    const int wbase = warp * 16;     // this warp's 16 query rows

    uint32_t af[2][4];               // [kstep][4 regs], Q * scale * log2e
    int ar0;                         // bias row code for row rA (rB = +8)
    {
        const float* qbase = qkv + b * plane + head * HD;
        const float qs = QK_SCALE * LOG2E;
        const int rA = wbase + g;
        const int rB = rA + 8;
        ar0 = ((rA >> 4) + 15) * 31 + (rA & 15) + 15;
        const int gA = (wh0 + (rA >> 4)) * 256 + ww0 + (rA & 15);
        const int gB = (wh0 + (rB >> 4)) * 256 + ww0 + (rB & 15);
        const float* qA = qbase + (long long)gA * DIMM;
        const float* qB = qbase + (long long)gB * DIMM;
        #pragma unroll
        for (int ks = 0; ks < 2; ks++) {
            const int c0 = ks * 16 + 2 * t;
            float2 f;
            f = *(const float2*)(qA + c0);
            af[ks][0] = pack_h2(f.x * qs, f.y * qs);
            f = *(const float2*)(qB + c0);
            af[ks][1] = pack_h2(f.x * qs, f.y * qs);
            f = *(const float2*)(qA + c0 + 8);
            af[ks][2] = pack_h2(f.x * qs, f.y * qs);
            f = *(const float2*)(qB + c0 + 8);
            af[ks][3] = pack_h2(f.x * qs, f.y * qs);
        }
    }

    __syncthreads();

    // ---------------- fragment base addresses (immediates per iter) -------
    const int lm = lane >> 3;
    const int lr = lane & 7;
    const uint32_t kaddr = smem_u32(&Ks[((lm >> 1) * 8 + lr) * KS_STRIDE + (lm & 1) * 8]);
    const uint32_t vaddr = smem_u32(&Vs[(lane & 7) * KS_STRIDE + (lane >> 3) * 8]);
    const uint32_t VROW8 = 8 * KS_STRIDE * 2;    // +8 j rows
    const uint32_t JSTEP = 16 * KS_STRIDE * 2;   // +16 rows per block

    // Bias pair-table base index; per-iteration offsets are immediates.
    const int i00 = ar0 - (2 * t + 1);

    float o[4][4] = {};       // [d-tile][4] fp32 accumulators
    float rs0 = 0.f, rs1 = 0.f;

    // ---------------- fully unrolled main loop (16 x 16-col blocks) -------
    #pragma unroll
    for (int it = 0; it < 16; it++) {
        const uint32_t ko = it * JSTEP;   // compile-time immediate
        const int      ib = i00 - 31 * it;

        // K fragments
        uint32_t bf0[4], bf1[4];
        ldsm4(bf0, kaddr + ko);
        ldsm4(bf1, kaddr + ko + 32);
        // V fragments (independent of K chain)
        uint32_t bvA[4], bvB[4];
        ldsm4t(bvA, vaddr + ko);
        ldsm4t(bvB, vaddr + ko + VROW8);

        // bias half2 pairs -> initialize f16 S accumulators
        uint32_t sc0 = bh[ib];           // (rA, cols c,c+1)
        uint32_t sc1 = bh[ib + 8];       // (rB, cols c,c+1)
        uint32_t sc2 = bh[ib - 8];       // (rA, cols c+8,c+9)
        uint32_t sc3 = sc0;              // (rB, cols c+8,c+9) == bh[ib]

        // S = Q K^T + bias   (fp16 accum, log2 units)
        MMAH(sc0, sc1, af[0], bf0[0], bf0[1]);
        MMAH(sc0, sc1, af[1], bf1[0], bf1[1]);
        MMAH(sc2, sc3, af[0], bf0[2], bf0[3]);
        MMAH(sc2, sc3, af[1], bf1[2], bf1[3]);

        // P = 2^S  (f16x2) — C-frags ARE the PV A-frags
        uint32_t pa[4];
        pa[0] = ex2h2(sc0);
        pa[1] = ex2h2(sc1);
        pa[2] = ex2h2(sc2);
        pa[3] = ex2h2(sc3);

        // row sums: pairwise in fp16, accumulate fp32
        const float2 fA = h22f2(hadd2u(pa[0], pa[2]));
        rs0 += fA.x + fA.y;
        const float2 fB = h22f2(hadd2u(pa[1], pa[3]));
        rs1 += fB.x + fB.y;

        // O += P * V
        MMAF(o[0], pa, bvA[0], bvB[0]);
        MMAF(o[1], pa, bvA[1], bvB[1]);
        MMAF(o[2], pa, bvA[2], bvB[2]);
        MMAF(o[3], pa, bvA[3], bvB[3]);
    }

    // ---------------- normalize and write output --------------------------
    rs0 += __shfl_xor_sync(0xFFFFFFFFu, rs0, 1);
    rs0 += __shfl_xor_sync(0xFFFFFFFFu, rs0, 2);
    rs1 += __shfl_xor_sync(0xFFFFFFFFu, rs1, 1);
    rs1 += __shfl_xor_sync(0xFFFFFFFFu, rs1, 2);
    const float inv0 = rcpf(rs0);
    const float inv1 = rcpf(rs1);

    const int rA = wbase + g;
    const int rB = rA + 8;
    const long long gA = b * 65536LL + (wh0 + (rA >> 4)) * 256 + ww0 + (rA & 15);
    const long long gB = b * 65536LL + (wh0 + (rB >> 4)) * 256 + ww0 + (rB & 15);
    float* oA = out + gA * DIMM + head * HD;
    float* oB = out + gB * DIMM + head * HD;
    #pragma unroll
    for (int dt = 0; dt < 4; dt++) {
        const int d = dt * 8 + 2 * t;
        *(float2*)(oA + d) = make_float2(o[dt][0] * inv0, o[dt][1] * inv0);
        *(float2*)(oB + d) = make_float2(o[dt][2] * inv1, o[dt][3] * inv1);
    }
}

extern "C" void kernel_launch(void* const* d_in, const int* in_sizes, int n_in,
                              void* d_out, int out_size)
{
    (void)in_sizes; (void)n_in; (void)out_size;
    const float* qkv        = (const float*)d_in[0];
    const float* bias_table = (const float*)d_in[1];
    float* out              = (float*)d_out;

    // 2 batches * 256 windows * 6 heads = 3072 CTAs, 512 threads each
    winattn_kernel<<<3072, 512>>>(qkv, bias_table, out);
}

// round 16
// speedup vs baseline: 1.1942x; 1.0026x over previous
#include <cuda_runtime.h>
#include <cuda_fp16.h>
#include <cstdint>

// Problem constants
#define HEADS   6
#define HD      32      // head_dim
#define DIMM    192
#define NWIN    256     // tokens per 16x16 window
#define KS_STRIDE 40    // half elements per K/V row in smem (80B rows, conflict-free)
#define LOG2E   1.4426950408889634f
#define QK_SCALE 0.17677669529663687f   // 32^-0.5

__device__ __forceinline__ float rcpf(float x) {
    float y; asm("rcp.approx.f32 %0, %1;" : "=f"(y) : "f"(x)); return y;
}
__device__ __forceinline__ uint32_t ex2h2(uint32_t a) {
    uint32_t d; asm("ex2.approx.f16x2 %0, %1;" : "=r"(d) : "r"(a)); return d;
}
__device__ __forceinline__ uint32_t hadd2u(uint32_t a, uint32_t b) {
    uint32_t d; asm("add.f16x2 %0, %1, %2;" : "=r"(d) : "r"(a), "r"(b)); return d;
}
__device__ __forceinline__ float2 h22f2(uint32_t h) {
    float2 f;
    asm("{\n\t.reg .f16 lo, hi;\n\tmov.b32 {lo, hi}, %2;\n\t"
        "cvt.f32.f16 %0, lo;\n\tcvt.f32.f16 %1, hi;\n\t}"
        : "=f"(f.x), "=f"(f.y) : "r"(h));
    return f;
}
// pack two floats into f16x2 register: lo = first arg
__device__ __forceinline__ uint32_t pack_h2(float lo, float hi) {
    uint32_t r;
    asm("cvt.rn.f16x2.f32 %0, %1, %2;" : "=r"(r) : "f"(hi), "f"(lo));
    return r;
}
__device__ __forceinline__ uint32_t smem_u32(const void* p) {
    uint32_t a;
    asm("{ .reg .u64 t; cvta.to.shared.u64 t, %1; cvt.u32.u64 %0, t; }"
        : "=r"(a) : "l"(p));
    return a;
}
__device__ __forceinline__ void ldsm4(uint32_t* r, uint32_t addr) {
    asm volatile("ldmatrix.sync.aligned.m8n8.x4.shared.b16 {%0,%1,%2,%3}, [%4];"
        : "=r"(r[0]), "=r"(r[1]), "=r"(r[2]), "=r"(r[3]) : "r"(addr));
}
__device__ __forceinline__ void ldsm4t(uint32_t* r, uint32_t addr) {
    asm volatile("ldmatrix.sync.aligned.m8n8.x4.trans.shared.b16 {%0,%1,%2,%3}, [%4];"
        : "=r"(r[0]), "=r"(r[1]), "=r"(r[2]), "=r"(r[3]) : "r"(addr));
}

// f16-accumulate MMA: {c0,c1} += A * B   (C/D are f16x2 pairs)
#define MMAH(c0, c1, a, b0, b1)                                               \
    asm("mma.sync.aligned.m16n8k16.row.col.f16.f16.f16.f16 "                  \
        "{%0,%1}, {%2,%3,%4,%5}, {%6,%7}, {%0,%1};"                           \
        : "+r"(c0), "+r"(c1)                                                  \
        : "r"((a)[0]), "r"((a)[1]), "r"((a)[2]), "r"((a)[3]),                 \
          "r"(b0), "r"(b1))

// f32-accumulate MMA: C += A * B
#define MMAF(c, a, b0, b1)                                                    \
    asm("mma.sync.aligned.m16n8k16.row.col.f32.f16.f16.f32 "                  \
        "{%0,%1,%2,%3}, {%4,%5,%6,%7}, {%8,%9}, {%0,%1,%2,%3};"               \
        : "+f"((c)[0]), "+f"((c)[1]), "+f"((c)[2]), "+f"((c)[3])              \
        : "r"((a)[0]), "r"((a)[1]), "r"((a)[2]), "r"((a)[3]),                 \
          "r"(b0), "r"(b1))

__global__ __launch_bounds__(512, 2)
void winattn_kernel(const float* __restrict__ qkv,
                    const float* __restrict__ bias_table,
                    float* __restrict__ out)
{
    __shared__ half     Ks[NWIN * KS_STRIDE];   // 20480 B: K, row-major (j, k)
    __shared__ half     Vs[NWIN * KS_STRIDE];   // 20480 B: V, row-major (j, d)
    __shared__ uint32_t bh[961];                //  3844 B: half2 (b[i+1], b[i]) * log2e

    const int tid  = threadIdx.x;
    const int bid  = blockIdx.x;
    const int head = bid % HEADS;
    const int win  = (bid / HEADS) & 255;
    const int b    = bid / (HEADS * 256);

    const int wh0 = (win >> 4) << 4;   // window top row in the image
    const int ww0 = (win & 15) << 4;   // window left col

    const long long plane = 65536LL * DIMM;
    const float* kbase = qkv + (2 + b) * plane + head * HD;
    const float* vbase = qkv + (4 + b) * plane + head * HD;

    // One K/V load chunk: 512 threads cover 64 pixels (8 thr/pixel).
    auto load_kv = [&](int vi) {
        const int p  = vi >> 3;            // window pixel
        const int c4 = (vi & 7) * 4;       // channel 0,4,...,28
        const int grow = (wh0 + (p >> 4)) * 256 + ww0 + (p & 15);
        {
            const float4 kv = *(const float4*)(kbase + (long long)grow * DIMM + c4);
            uint2 kk; kk.x = pack_h2(kv.x, kv.y); kk.y = pack_h2(kv.z, kv.w);
            *(uint2*)&Ks[p * KS_STRIDE + c4] = kk;
        }
        {
            const float4 vv = *(const float4*)(vbase + (long long)grow * DIMM + c4);
            uint2 vk; vk.x = pack_h2(vv.x, vv.y); vk.y = pack_h2(vv.z, vv.w);
            *(uint2*)&Vs[p * KS_STRIDE + c4] = vk;
        }
    };

    // ---------------- per-warp Q fragments (16 rows per warp) -------------
    const int warp  = tid >> 5;
    const int lane  = tid & 31;
    const int g     = lane >> 2;     // groupID 0..7
    const int t     = lane & 3;      // thread-in-group
    const int wbase = warp * 16;     // this warp's 16 query rows

    uint32_t af[2][4];               // [kstep][4 regs], Q * scale * log2e
    int ar0;                         // bias row code for row rA (rB = +8)
    {
        const float* qbase = qkv + b * plane + head * HD;
        const float qs = QK_SCALE * LOG2E;
        const int rA = wbase + g;
        const int rB = rA + 8;
        ar0 = ((rA >> 4) + 15) * 31 + (rA & 15) + 15;
        const int gA = (wh0 + (rA >> 4)) * 256 + ww0 + (rA & 15);
        const int gB = (wh0 + (rB >> 4)) * 256 + ww0 + (rB & 15);
        const float* qA = qbase + (long long)gA * DIMM;
        const float* qB = qbase + (long long)gB * DIMM;
        #pragma unroll
        for (int ks = 0; ks < 2; ks++) {
            const int c0 = ks * 16 + 2 * t;
            float2 f;
            f = *(const float2*)(qA + c0);
            af[ks][0] = pack_h2(f.x * qs, f.y * qs);
            f = *(const float2*)(qB + c0);
            af[ks][1] = pack_h2(f.x * qs, f.y * qs);
            f = *(const float2*)(qA + c0 + 8);
            af[ks][2] = pack_h2(f.x * qs, f.y * qs);
            f = *(const float2*)(qB + c0 + 8);
            af[ks][3] = pack_h2(f.x * qs, f.y * qs);
        }
    }

    // ---------------- phase A: K/V rows j<128, bias table ------------------
    load_kv(tid);
    load_kv(tid + 512);
    for (int i = tid; i < 961; i += 512) {
        const float lo = bias_table[i * HEADS + head] * LOG2E;
        const float hi = (i < 960 ? bias_table[(i + 1) * HEADS + head] : 0.f) * LOG2E;
        bh[i] = pack_h2(hi, lo);   // low half = hi-index value
    }
    __syncthreads();

    // ---------------- fragment base addresses ------------------------------
    const int lm = lane >> 3;
    const int lr = lane & 7;
    const uint32_t kaddr = smem_u32(&Ks[((lm >> 1) * 8 + lr) * KS_STRIDE + (lm & 1) * 8]);
    const uint32_t vaddr = smem_u32(&Vs[(lane & 7) * KS_STRIDE + (lane >> 3) * 8]);
    const uint32_t VROW8 = 8 * KS_STRIDE * 2;    // +8 j rows
    const uint32_t JSTEP = 16 * KS_STRIDE * 2;   // +16 rows per block

    const int i00 = ar0 - (2 * t + 1);

    float o[4][4] = {};       // [d-tile][4] fp32 accumulators
    float rs0 = 0.f, rs1 = 0.f;

    // One 16-column attention block (identical math to the 121.3us kernel)
    auto block = [&](int it) {
        const uint32_t ko = (uint32_t)it * JSTEP;
        const int      ib = i00 - 31 * it;

        uint32_t bf0[4], bf1[4];
        ldsm4(bf0, kaddr + ko);
        ldsm4(bf1, kaddr + ko + 32);
        uint32_t bvA[4], bvB[4];
        ldsm4t(bvA, vaddr + ko);
        ldsm4t(bvB, vaddr + ko + VROW8);

        uint32_t sc0 = bh[ib];
        uint32_t sc1 = bh[ib + 8];
        uint32_t sc2 = bh[ib - 8];
        uint32_t sc3 = sc0;

        MMAH(sc0, sc1, af[0], bf0[0], bf0[1]);
        MMAH(sc0, sc1, af[1], bf1[0], bf1[1]);
        MMAH(sc2, sc3, af[0], bf0[2], bf0[3]);
        MMAH(sc2, sc3, af[1], bf1[2], bf1[3]);

        uint32_t pa[4];
        pa[0] = ex2h2(sc0);
        pa[1] = ex2h2(sc1);
        pa[2] = ex2h2(sc2);
        pa[3] = ex2h2(sc3);

        const float2 fA = h22f2(hadd2u(pa[0], pa[2]));
        rs0 += fA.x + fA.y;
        const float2 fB = h22f2(hadd2u(pa[1], pa[3]));
        rs1 += fB.x + fB.y;

        MMAF(o[0], pa, bvA[0], bvB[0]);
        MMAF(o[1], pa, bvA[1], bvB[1]);
        MMAF(o[2], pa, bvA[2], bvB[2]);
        MMAF(o[3], pa, bvA[3], bvB[3]);
    };

    // ---------------- half 0 compute, phase-B loads interleaved ------------
    block(0);  block(1);
    load_kv(tid + 1024);           // K/V rows j in [128,192)
    block(2);  block(3);
    load_kv(tid + 1536);           // K/V rows j in [192,256)
    block(4);  block(5);  block(6);  block(7);
    __syncthreads();               // phase-B stores visible to all warps

    // ---------------- half 1 compute ---------------------------------------
    block(8);  block(9);  block(10); block(11);
    block(12); block(13); block(14); block(15);

    // ---------------- normalize and write output --------------------------
    rs0 += __shfl_xor_sync(0xFFFFFFFFu, rs0, 1);
    rs0 += __shfl_xor_sync(0xFFFFFFFFu, rs0, 2);
    rs1 += __shfl_xor_sync(0xFFFFFFFFu, rs1, 1);
    rs1 += __shfl_xor_sync(0xFFFFFFFFu, rs1, 2);
    const float inv0 = rcpf(rs0);
    const float inv1 = rcpf(rs1);

    const int rA = wbase + g;
    const int rB = rA + 8;
    const long long gA = b * 65536LL + (wh0 + (rA >> 4)) * 256 + ww0 + (rA & 15);
    const long long gB = b * 65536LL + (wh0 + (rB >> 4)) * 256 + ww0 + (rB & 15);
    float* oA = out + gA * DIMM + head * HD;
    float* oB = out + gB * DIMM + head * HD;
    #pragma unroll
    for (int dt = 0; dt < 4; dt++) {
        const int d = dt * 8 + 2 * t;
        *(float2*)(oA + d) = make_float2(o[dt][0] * inv0, o[dt][1] * inv0);
        *(float2*)(oB + d) = make_float2(o[dt][2] * inv1, o[dt][3] * inv1);
    }
}

extern "C" void kernel_launch(void* const* d_in, const int* in_sizes, int n_in,
                              void* d_out, int out_size)
{
    (void)in_sizes; (void)n_in; (void)out_size;
    const float* qkv        = (const float*)d_in[0];
    const float* bias_table = (const float*)d_in[1];
    float* out              = (float*)d_out;

    // 2 batches * 256 windows * 6 heads = 3072 CTAs, 512 threads each
    winattn_kernel<<<3072, 512>>>(qkv, bias_table, out);
}

// round 17
// speedup vs baseline: 1.2800x; 1.0718x over previous
#include <cuda_runtime.h>
#include <cuda_fp16.h>
#include <cstdint>

// Problem constants
#define HEADS   6
#define HD      32      // head_dim
#define DIMM    192
#define NWIN    256     // tokens per 16x16 window
#define KS_STRIDE 40    // half elements per K/V row in smem (80B rows, conflict-free)
#define LOG2E   1.4426950408889634f
#define QK_SCALE 0.17677669529663687f   // 32^-0.5

__device__ __forceinline__ float rcpf(float x) {
    float y; asm("rcp.approx.f32 %0, %1;" : "=f"(y) : "f"(x)); return y;
}
__device__ __forceinline__ uint32_t ex2h2(uint32_t a) {
    uint32_t d; asm("ex2.approx.f16x2 %0, %1;" : "=r"(d) : "r"(a)); return d;
}
// pack two floats into f16x2 register: lo = first arg
__device__ __forceinline__ uint32_t pack_h2(float lo, float hi) {
    uint32_t r;
    asm("cvt.rn.f16x2.f32 %0, %1, %2;" : "=r"(r) : "f"(hi), "f"(lo));
    return r;
}
__device__ __forceinline__ uint32_t smem_u32(const void* p) {
    uint32_t a;
    asm("{ .reg .u64 t; cvta.to.shared.u64 t, %1; cvt.u32.u64 %0, t; }"
        : "=r"(a) : "l"(p));
    return a;
}
__device__ __forceinline__ void ldsm4(uint32_t* r, uint32_t addr) {
    asm volatile("ldmatrix.sync.aligned.m8n8.x4.shared.b16 {%0,%1,%2,%3}, [%4];"
        : "=r"(r[0]), "=r"(r[1]), "=r"(r[2]), "=r"(r[3]) : "r"(addr));
}
__device__ __forceinline__ void ldsm4t(uint32_t* r, uint32_t addr) {
    asm volatile("ldmatrix.sync.aligned.m8n8.x4.trans.shared.b16 {%0,%1,%2,%3}, [%4];"
        : "=r"(r[0]), "=r"(r[1]), "=r"(r[2]), "=r"(r[3]) : "r"(addr));
}

// f16-accumulate MMA: {c0,c1} += A * B   (C/D are f16x2 pairs)
#define MMAH(c0, c1, a, b0, b1)                                               \
    asm("mma.sync.aligned.m16n8k16.row.col.f16.f16.f16.f16 "                  \
        "{%0,%1}, {%2,%3,%4,%5}, {%6,%7}, {%0,%1};"                           \
        : "+r"(c0), "+r"(c1)                                                  \
        : "r"((a)[0]), "r"((a)[1]), "r"((a)[2]), "r"((a)[3]),                 \
          "r"(b0), "r"(b1))

// f32-accumulate MMA: C += A * B
#define MMAF(c, a, b0, b1)                                                    \
    asm("mma.sync.aligned.m16n8k16.row.col.f32.f16.f16.f32 "                  \
        "{%0,%1,%2,%3}, {%4,%5,%6,%7}, {%8,%9}, {%0,%1,%2,%3};"               \
        : "+f"((c)[0]), "+f"((c)[1]), "+f"((c)[2]), "+f"((c)[3])              \
        : "r"((a)[0]), "r"((a)[1]), "r"((a)[2]), "r"((a)[3]),                 \
          "r"(b0), "r"(b1))

__global__ __launch_bounds__(512, 2)
void winattn_kernel(const float* __restrict__ qkv,
                    const float* __restrict__ bias_table,
                    float* __restrict__ out)
{
    __shared__ __align__(16) half Ks[NWIN * KS_STRIDE];  // 20480 B: K (j, k)
    __shared__ __align__(16) half Vs[NWIN * KS_STRIDE];  // 20480 B: V (j, d)
    __shared__ uint32_t bh[961];                //  3844 B: half2 (b[i+1], b[i]) * log2e

    const int tid  = threadIdx.x;
    const int bid  = blockIdx.x;
    const int head = bid % HEADS;
    const int win  = (bid / HEADS) & 255;
    const int b    = bid / (HEADS * 256);

    const int wh0 = (win >> 4) << 4;   // window top row in the image
    const int ww0 = (win & 15) << 4;   // window left col

    const long long plane = 65536LL * DIMM;
    const float* kbase = qkv + (2 + b) * plane + head * HD;
    const float* vbase = qkv + (4 + b) * plane + head * HD;

    // One K/V load slot: 4 threads per pixel, 8 channels each, STS.128.
    auto load_kv = [&](int vi) {
        const int p  = vi >> 2;            // window pixel
        const int c8 = (vi & 3) * 8;       // channel 0,8,16,24
        const int grow = (wh0 + (p >> 4)) * 256 + ww0 + (p & 15);
        {
            const float4 k0 = *(const float4*)(kbase + (long long)grow * DIMM + c8);
            const float4 k1 = *(const float4*)(kbase + (long long)grow * DIMM + c8 + 4);
            uint4 kk;
            kk.x = pack_h2(k0.x, k0.y); kk.y = pack_h2(k0.z, k0.w);
            kk.z = pack_h2(k1.x, k1.y); kk.w = pack_h2(k1.z, k1.w);
            *(uint4*)&Ks[p * KS_STRIDE + c8] = kk;
        }
        {
            const float4 v0 = *(const float4*)(vbase + (long long)grow * DIMM + c8);
            const float4 v1 = *(const float4*)(vbase + (long long)grow * DIMM + c8 + 4);
            uint4 vk;
            vk.x = pack_h2(v0.x, v0.y); vk.y = pack_h2(v0.z, v0.w);
            vk.z = pack_h2(v1.x, v1.y); vk.w = pack_h2(v1.z, v1.w);
            *(uint4*)&Vs[p * KS_STRIDE + c8] = vk;
        }
    };

    // ---------------- per-warp Q fragments (16 rows per warp) -------------
    const int warp  = tid >> 5;
    const int lane  = tid & 31;
    const int g     = lane >> 2;     // groupID 0..7
    const int t     = lane & 3;      // thread-in-group
    const int wbase = warp * 16;     // this warp's 16 query rows

    uint32_t af[2][4];               // [kstep][4 regs], Q * scale * log2e
    int ar0;                         // bias row code for row rA (rB = +8)
    {
        const float* qbase = qkv + b * plane + head * HD;
        const float qs = QK_SCALE * LOG2E;
        const int rA = wbase + g;
        const int rB = rA + 8;
        ar0 = ((rA >> 4) + 15) * 31 + (rA & 15) + 15;
        const int gA = (wh0 + (rA >> 4)) * 256 + ww0 + (rA & 15);
        const int gB = (wh0 + (rB >> 4)) * 256 + ww0 + (rB & 15);
        const float* qA = qbase + (long long)gA * DIMM;
        const float* qB = qbase + (long long)gB * DIMM;
        #pragma unroll
        for (int ks = 0; ks < 2; ks++) {
            const int c0 = ks * 16 + 2 * t;
            float2 f;
            f = *(const float2*)(qA + c0);
            af[ks][0] = pack_h2(f.x * qs, f.y * qs);
            f = *(const float2*)(qB + c0);
            af[ks][1] = pack_h2(f.x * qs, f.y * qs);
            f = *(const float2*)(qA + c0 + 8);
            af[ks][2] = pack_h2(f.x * qs, f.y * qs);
            f = *(const float2*)(qB + c0 + 8);
            af[ks][3] = pack_h2(f.x * qs, f.y * qs);
        }
    }

    // ---------------- phase A: K/V rows j<128, bias table ------------------
    load_kv(tid);                      // pixels 0..127
    for (int i = tid; i < 961; i += 512) {
        const float lo = bias_table[i * HEADS + head] * LOG2E;
        const float hi = (i < 960 ? bias_table[(i + 1) * HEADS + head] : 0.f) * LOG2E;
        bh[i] = pack_h2(hi, lo);   // low half = hi-index value
    }
    __syncthreads();

    // ---------------- fragment base addresses ------------------------------
    const int lm = lane >> 3;
    const int lr = lane & 7;
    const uint32_t kaddr = smem_u32(&Ks[((lm >> 1) * 8 + lr) * KS_STRIDE + (lm & 1) * 8]);
    const uint32_t vaddr = smem_u32(&Vs[(lane & 7) * KS_STRIDE + (lane >> 3) * 8]);
    const uint32_t VROW8 = 8 * KS_STRIDE * 2;    // +8 j rows
    const uint32_t JSTEP = 16 * KS_STRIDE * 2;   // +16 rows per block

    const int i00 = ar0 - (2 * t + 1);
    const uint32_t ONE2 = 0x3C003C00u;           // half2(1.0, 1.0)

    float o[4][4]  = {};      // [d-tile][4] fp32 accumulators
    float rso[4]   = {};      // row-sum C-frag: rso[0]=rows rA, rso[2]=rows rB

    // One 16-column attention block
    auto block = [&](int it) {
        const uint32_t ko = (uint32_t)it * JSTEP;
        const int      ib = i00 - 31 * it;

        uint32_t bf0[4], bf1[4];
        ldsm4(bf0, kaddr + ko);
        ldsm4(bf1, kaddr + ko + 32);
        uint32_t bvA[4], bvB[4];
        ldsm4t(bvA, vaddr + ko);
        ldsm4t(bvB, vaddr + ko + VROW8);

        uint32_t sc0 = bh[ib];
        uint32_t sc1 = bh[ib + 8];
        uint32_t sc2 = bh[ib - 8];
        uint32_t sc3 = sc0;

        // S = Q K^T + bias   (fp16 accum, log2 units)
        MMAH(sc0, sc1, af[0], bf0[0], bf0[1]);
        MMAH(sc0, sc1, af[1], bf1[0], bf1[1]);
        MMAH(sc2, sc3, af[0], bf0[2], bf0[3]);
        MMAH(sc2, sc3, af[1], bf1[2], bf1[3]);

        // P = 2^S  (f16x2) — C-frags ARE the PV A-frags
        uint32_t pa[4];
        pa[0] = ex2h2(sc0);
        pa[1] = ex2h2(sc1);
        pa[2] = ex2h2(sc2);
        pa[3] = ex2h2(sc3);

        // row sums via ones-column MMA: every column of C = rowsum(P)
        MMAF(rso, pa, ONE2, ONE2);

        // O += P * V
        MMAF(o[0], pa, bvA[0], bvB[0]);
        MMAF(o[1], pa, bvA[1], bvB[1]);
        MMAF(o[2], pa, bvA[2], bvB[2]);
        MMAF(o[3], pa, bvA[3], bvB[3]);
    };

    // ---------------- half 0 compute, phase-B load interleaved -------------
    block(0);  block(1);
    load_kv(tid + 512);            // pixels 128..255
    block(2);  block(3);  block(4);  block(5);  block(6);  block(7);
    __syncthreads();               // phase-B stores visible to all warps

    // ---------------- half 1 compute ---------------------------------------
    block(8);  block(9);  block(10); block(11);
    block(12); block(13); block(14); block(15);

    // ---------------- normalize and write output --------------------------
    // rso[0] / rso[2] already hold the full row sums (no shfl needed).
    const float inv0 = rcpf(rso[0]);
    const float inv1 = rcpf(rso[2]);

    const int rA = wbase + g;
    const int rB = rA + 8;
    const long long gA = b * 65536LL + (wh0 + (rA >> 4)) * 256 + ww0 + (rA & 15);
    const long long gB = b * 65536LL + (wh0 + (rB >> 4)) * 256 + ww0 + (rB & 15);
    float* oA = out + gA * DIMM + head * HD;
    float* oB = out + gB * DIMM + head * HD;
    #pragma unroll
    for (int dt = 0; dt < 4; dt++) {
        const int d = dt * 8 + 2 * t;
        *(float2*)(oA + d) = make_float2(o[dt][0] * inv0, o[dt][1] * inv0);
        *(float2*)(oB + d) = make_float2(o[dt][2] * inv1, o[dt][3] * inv1);
    }
}

extern "C" void kernel_launch(void* const* d_in, const int* in_sizes, int n_in,
                              void* d_out, int out_size)
{
    (void)in_sizes; (void)n_in; (void)out_size;
    const float* qkv        = (const float*)d_in[0];
    const float* bias_table = (const float*)d_in[1];
    float* out              = (float*)d_out;

    // 2 batches * 256 windows * 6 heads = 3072 CTAs, 512 threads each
    winattn_kernel<<<3072, 512>>>(qkv, bias_table, out);
}